// round 2
// baseline (speedup 1.0000x reference)
#include <cuda_runtime.h>
#include <math.h>

// Problem constants
#define Bb 128
#define Tt 1024
#define Ll 2
#define Dd 512
#define Hh 512
#define G4 2048   // 4*H

// Tile config
#define BM 64     // batch rows per block
#define NH 16     // hidden units per block
#define BN 64     // gate columns per block = 4*NH
#define BK 16     // K tile
#define NBLOCKS 128   // (Hh/NH) * (Bb/BM) * Ll = 32*2*2

// Persistent device state (allocation-free scratch).
// h double-buffered per layer: buffer (t&1) holds state going INTO step t.
__device__ float g_h[Ll][2][Bb][Hh];
__device__ float g_c[Ll][Bb][Hh];
// layer-0 nh stream (unmasked), double-buffered by step parity
__device__ float g_hbuf[2][Bb][Hh];
// software grid barrier (monotonic phase; survives graph replays because each
// launch reads the current phase as its base)
__device__ unsigned int g_bar_count;
__device__ unsigned int g_bar_phase;

__device__ __forceinline__ float sigf(float v) {
    return 1.0f / (1.0f + __expf(-v));
}

// Grid-wide barrier. Safe because all NBLOCKS blocks are co-resident
// (128 blocks <= 148 SMs, one wave). Monotonic phase counter, cumulative
// fences via __syncthreads + __threadfence.
__device__ __forceinline__ void grid_barrier(unsigned int target) {
    __syncthreads();
    if (threadIdx.x == 0) {
        __threadfence();
        unsigned int old = atomicAdd(&g_bar_count, 1u);
        if (old == NBLOCKS - 1) {
            g_bar_count = 0;
            __threadfence();
            atomicAdd(&g_bar_phase, 1u);
        } else {
            while (*(volatile unsigned int*)&g_bar_phase < target) { }
            __threadfence();
        }
    }
    __syncthreads();
}

// One persistent kernel runs the whole 2-layer scan.
// Super-step s: layer-0 blocks compute t=s, layer-1 blocks compute t=s-1
// (software pipeline: layer 1 consumes layer 0's nh from the previous
// super-step, so within a super-step the layers are independent).
__global__ void __launch_bounds__(256, 1)
lstm_persistent(const float* __restrict__ x,
                const float* __restrict__ h_masks,
                const float* __restrict__ Wi,
                const float* __restrict__ Wh,
                const float* __restrict__ bias,
                const float* __restrict__ c0,
                const float* __restrict__ h0,
                const int*   __restrict__ lengths,
                float* __restrict__ out)
{
    __shared__ float As[BK][BM + 4];   // A transposed: As[k][m]  (row = 68 floats = 17*16B, float4-safe)
    __shared__ float Bs[BK][BN + 4];   // Bs[k][n]
    __shared__ float Zs[BM][BN + 4];   // z tile for gate regroup
    __shared__ unsigned int s_base;

    const int tid   = threadIdx.x;
    const int layer = blockIdx.z;
    const int j0    = blockIdx.x * NH;   // hidden-unit base
    const int m0    = blockIdx.y * BM;   // batch base
    const int gb    = (blockIdx.z * gridDim.y + blockIdx.y) * gridDim.x + blockIdx.x;

    if (tid == 0) s_base = *(volatile unsigned int*)&g_bar_phase;

    // ---- cooperative state init (c0, h0 into parity-0 buffers) ----
    {
        const int total = Ll * Bb * Hh;
        for (int i = gb * 256 + tid; i < total; i += NBLOCKS * 256) {
            const int l = i / (Bb * Hh);
            const int r = i % (Bb * Hh);
            (&g_c[0][0][0])[i]       = c0[i];
            (&g_h[l][0][0][0])[r]    = h0[i];
        }
    }
    __syncthreads();   // make s_base visible block-wide
    const unsigned int base = s_base;
    unsigned int bar = 1;
    grid_barrier(base + bar++);   // init complete

    // ---- per-block constants ----
    const float* __restrict__ Wil = Wi + (size_t)layer * Dd * G4;
    const float* __restrict__ Whl = Wh + (size_t)layer * Hh * G4;
    const float* __restrict__ msk = h_masks + layer * Bb * Hh;
    const float* __restrict__ bl  = bias + layer * G4;

    // load mappings
    const int aM  = tid >> 2;            // 0..63
    const int aK4 = (tid & 3) * 4;       // 0,4,8,12
    const int bK  = tid >> 4;            // 0..15
    const int bN4 = (tid & 15) * 4;      // 0..60 step 4
    const int gate = bN4 >> 4;           // 0..3
    const int col  = gate * Hh + j0 + (bN4 & 15);
    const int ty  = tid >> 4;            // microtile row group
    const int tx  = tid & 15;            // microtile col group
    const int arow = m0 + aM;

    // epilogue mapping
    const int em   = tid >> 2;           // 0..63
    const int ejj0 = (tid & 3) * 4;
    const int ebrow = m0 + em;
    const int elen  = lengths[ebrow];

    for (int s = 0; s <= Tt; ++s) {
        const int t = (layer == 0) ? s : (s - 1);
        if (t >= 0 && t < Tt) {
            const float* __restrict__ hin  = &g_h[layer][t & 1][0][0];
            float*       __restrict__ hout = &g_h[layer][(t + 1) & 1][0][0];
            const float* __restrict__ vin;
            size_t vstride;
            if (layer == 0) { vin = x + (size_t)t * Dd; vstride = (size_t)Tt * Dd; }
            else            { vin = &g_hbuf[t & 1][0][0]; vstride = Hh; }

            float acc[4][4];
#pragma unroll
            for (int i = 0; i < 4; ++i)
#pragma unroll
                for (int j = 0; j < 4; ++j) acc[i][j] = 0.0f;

#pragma unroll 1
            for (int kt = 0; kt < (Dd + Hh) / BK; ++kt) {
                const int kb = kt * BK;

                // A tile: concat[input, h*mask]
                float4 av;
                const int k = kb + aK4;
                if (k < Dd) {
                    av = *(const float4*)(vin + (size_t)arow * vstride + k);
                } else {
                    const int kr = k - Dd;
                    const float4 hv = *(const float4*)(hin + arow * Hh + kr);
                    const float4 mv = *(const float4*)(msk + arow * Hh + kr);
                    av = make_float4(hv.x * mv.x, hv.y * mv.y, hv.z * mv.z, hv.w * mv.w);
                }
                As[aK4 + 0][aM] = av.x;
                As[aK4 + 1][aM] = av.y;
                As[aK4 + 2][aM] = av.z;
                As[aK4 + 3][aM] = av.w;

                // B tile: Wi rows for k<D, Wh rows for k>=D
                float4 bv;
                if (kb < Dd) {
                    bv = *(const float4*)(Wil + (size_t)(kb + bK) * G4 + col);
                } else {
                    bv = *(const float4*)(Whl + (size_t)(kb - Dd + bK) * G4 + col);
                }
                *(float4*)&Bs[bK][bN4] = bv;

                __syncthreads();

#pragma unroll
                for (int kk = 0; kk < BK; ++kk) {
                    const float4 a4 = *(const float4*)&As[kk][ty * 4];
                    const float4 b4 = *(const float4*)&Bs[kk][tx * 4];
                    const float ar[4] = {a4.x, a4.y, a4.z, a4.w};
                    const float br[4] = {b4.x, b4.y, b4.z, b4.w};
#pragma unroll
                    for (int i = 0; i < 4; ++i)
#pragma unroll
                        for (int j = 0; j < 4; ++j)
                            acc[i][j] = fmaf(ar[i], br[j], acc[i][j]);
                }
                __syncthreads();
            }

            // regroup gates through shared memory
#pragma unroll
            for (int i = 0; i < 4; ++i)
#pragma unroll
                for (int j = 0; j < 4; ++j)
                    Zs[ty * 4 + i][tx * 4 + j] = acc[i][j];
            __syncthreads();

            const bool keep = (t < elen);
#pragma unroll
            for (int e = 0; e < 4; ++e) {
                const int jj = ejj0 + e;
                const int j  = j0 + jj;
                const float zi = Zs[em][jj]      + bl[j];
                const float zf = Zs[em][16 + jj] + bl[Hh + j];
                const float zg = Zs[em][32 + jj] + bl[2 * Hh + j];
                const float zo = Zs[em][48 + jj] + bl[3 * Hh + j];

                const float ig = sigf(zi);
                const float fg = sigf(zf);
                const float gg = tanhf(zg);
                const float og = sigf(zo);

                const float cold = g_c[layer][ebrow][j];
                const float nc = fg * cold + ig * gg;
                const float nh = og * tanhf(nc);

                g_c[layer][ebrow][j] = keep ? nc : cold;
                const float hold = hin[ebrow * Hh + j];
                hout[ebrow * Hh + j] = keep ? nh : hold;

                if (layer == 0) {
                    g_hbuf[s & 1][ebrow][j] = nh;                 // unmasked nh feeds layer 1
                } else {
                    out[((size_t)ebrow * Tt + t) * Hh + j] = nh;  // top-layer output
                }
            }
            __syncthreads();   // protect Zs before next iteration reuses it
        }
        grid_barrier(base + bar++);
    }
}

extern "C" void kernel_launch(void* const* d_in, const int* in_sizes, int n_in,
                              void* d_out, int out_size) {
    const float* x       = (const float*)d_in[0];
    const float* h_masks = (const float*)d_in[1];
    const float* Wi      = (const float*)d_in[2];
    const float* Wh      = (const float*)d_in[3];
    const float* bias    = (const float*)d_in[4];
    const float* c0      = (const float*)d_in[5];
    const float* h0      = (const float*)d_in[6];
    const int*   lengths = (const int*)d_in[7];
    float* out = (float*)d_out;

    (void)in_sizes; (void)n_in; (void)out_size;

    dim3 grid(Hh / NH, Bb / BM, Ll);  // (32, 2, 2) = 128 blocks, one wave
    lstm_persistent<<<grid, 256>>>(x, h_masks, Wi, Wh, bias, c0, h0, lengths, out);
}

// round 3
// speedup vs baseline: 1.0025x; 1.0025x over previous
#include <cuda_runtime.h>
#include <math.h>

// Problem constants
#define Bb 128
#define Tt 1024
#define Ll 2
#define Dd 512
#define Hh 512
#define G4 2048   // 4*H

// Tile config
#define BM 64     // batch rows per block
#define NH 16     // hidden units per block
#define BN 64     // gate columns per block = 4*NH
#define BK 16     // K tile
#define NBLOCKS 128   // (Hh/NH) * (Bb/BM) * Ll = 32*2*2

// Persistent device state (allocation-free scratch).
// h double-buffered per layer: buffer (t&1) holds state going INTO step t.
__device__ float g_h[Ll][2][Bb][Hh];
__device__ float g_c[Ll][Bb][Hh];
// layer-0 nh stream (unmasked), double-buffered by step parity
__device__ float g_hbuf[2][Bb][Hh];
// software grid barrier (monotonic phase; survives graph replays because each
// launch reads the current phase as its base)
__device__ unsigned int g_bar_count;
__device__ unsigned int g_bar_phase;

__device__ __forceinline__ float sigf(float v) {
    return 1.0f / (1.0f + __expf(-v));
}

// Grid-wide barrier. Safe because all NBLOCKS blocks are co-resident
// (128 blocks <= 148 SMs, one wave). Monotonic phase counter, cumulative
// fences via __syncthreads + __threadfence.
__device__ __forceinline__ void grid_barrier(unsigned int target) {
    __syncthreads();
    if (threadIdx.x == 0) {
        __threadfence();
        unsigned int old = atomicAdd(&g_bar_count, 1u);
        if (old == NBLOCKS - 1) {
            g_bar_count = 0;
            __threadfence();
            atomicAdd(&g_bar_phase, 1u);
        } else {
            while (*(volatile unsigned int*)&g_bar_phase < target) { }
            __threadfence();
        }
    }
    __syncthreads();
}

// One persistent kernel runs the whole 2-layer scan.
// Super-step s: layer-0 blocks compute t=s, layer-1 blocks compute t=s-1
// (software pipeline: layer 1 consumes layer 0's nh from the previous
// super-step, so within a super-step the layers are independent).
__global__ void __launch_bounds__(256, 1)
lstm_persistent(const float* __restrict__ x,
                const float* __restrict__ h_masks,
                const float* __restrict__ Wi,
                const float* __restrict__ Wh,
                const float* __restrict__ bias,
                const float* __restrict__ c0,
                const float* __restrict__ h0,
                const int*   __restrict__ lengths,
                float* __restrict__ out)
{
    __shared__ float As[BK][BM + 4];   // A transposed: As[k][m]  (row = 68 floats = 17*16B, float4-safe)
    __shared__ float Bs[BK][BN + 4];   // Bs[k][n]
    __shared__ float Zs[BM][BN + 4];   // z tile for gate regroup
    __shared__ unsigned int s_base;

    const int tid   = threadIdx.x;
    const int layer = blockIdx.z;
    const int j0    = blockIdx.x * NH;   // hidden-unit base
    const int m0    = blockIdx.y * BM;   // batch base
    const int gb    = (blockIdx.z * gridDim.y + blockIdx.y) * gridDim.x + blockIdx.x;

    if (tid == 0) s_base = *(volatile unsigned int*)&g_bar_phase;

    // ---- cooperative state init (c0, h0 into parity-0 buffers) ----
    {
        const int total = Ll * Bb * Hh;
        for (int i = gb * 256 + tid; i < total; i += NBLOCKS * 256) {
            const int l = i / (Bb * Hh);
            const int r = i % (Bb * Hh);
            (&g_c[0][0][0])[i]       = c0[i];
            (&g_h[l][0][0][0])[r]    = h0[i];
        }
    }
    __syncthreads();   // make s_base visible block-wide
    const unsigned int base = s_base;
    unsigned int bar = 1;
    grid_barrier(base + bar++);   // init complete

    // ---- per-block constants ----
    const float* __restrict__ Wil = Wi + (size_t)layer * Dd * G4;
    const float* __restrict__ Whl = Wh + (size_t)layer * Hh * G4;
    const float* __restrict__ msk = h_masks + layer * Bb * Hh;
    const float* __restrict__ bl  = bias + layer * G4;

    // load mappings
    const int aM  = tid >> 2;            // 0..63
    const int aK4 = (tid & 3) * 4;       // 0,4,8,12
    const int bK  = tid >> 4;            // 0..15
    const int bN4 = (tid & 15) * 4;      // 0..60 step 4
    const int gate = bN4 >> 4;           // 0..3
    const int col  = gate * Hh + j0 + (bN4 & 15);
    const int ty  = tid >> 4;            // microtile row group
    const int tx  = tid & 15;            // microtile col group
    const int arow = m0 + aM;

    // epilogue mapping
    const int em   = tid >> 2;           // 0..63
    const int ejj0 = (tid & 3) * 4;
    const int ebrow = m0 + em;
    const int elen  = lengths[ebrow];

    for (int s = 0; s <= Tt; ++s) {
        const int t = (layer == 0) ? s : (s - 1);
        if (t >= 0 && t < Tt) {
            const float* __restrict__ hin  = &g_h[layer][t & 1][0][0];
            float*       __restrict__ hout = &g_h[layer][(t + 1) & 1][0][0];
            const float* __restrict__ vin;
            size_t vstride;
            if (layer == 0) { vin = x + (size_t)t * Dd; vstride = (size_t)Tt * Dd; }
            else            { vin = &g_hbuf[t & 1][0][0]; vstride = Hh; }

            float acc[4][4];
#pragma unroll
            for (int i = 0; i < 4; ++i)
#pragma unroll
                for (int j = 0; j < 4; ++j) acc[i][j] = 0.0f;

#pragma unroll 1
            for (int kt = 0; kt < (Dd + Hh) / BK; ++kt) {
                const int kb = kt * BK;

                // A tile: concat[input, h*mask]
                float4 av;
                const int k = kb + aK4;
                if (k < Dd) {
                    av = *(const float4*)(vin + (size_t)arow * vstride + k);
                } else {
                    const int kr = k - Dd;
                    const float4 hv = *(const float4*)(hin + arow * Hh + kr);
                    const float4 mv = *(const float4*)(msk + arow * Hh + kr);
                    av = make_float4(hv.x * mv.x, hv.y * mv.y, hv.z * mv.z, hv.w * mv.w);
                }
                As[aK4 + 0][aM] = av.x;
                As[aK4 + 1][aM] = av.y;
                As[aK4 + 2][aM] = av.z;
                As[aK4 + 3][aM] = av.w;

                // B tile: Wi rows for k<D, Wh rows for k>=D
                float4 bv;
                if (kb < Dd) {
                    bv = *(const float4*)(Wil + (size_t)(kb + bK) * G4 + col);
                } else {
                    bv = *(const float4*)(Whl + (size_t)(kb - Dd + bK) * G4 + col);
                }
                *(float4*)&Bs[bK][bN4] = bv;

                __syncthreads();

#pragma unroll
                for (int kk = 0; kk < BK; ++kk) {
                    const float4 a4 = *(const float4*)&As[kk][ty * 4];
                    const float4 b4 = *(const float4*)&Bs[kk][tx * 4];
                    const float ar[4] = {a4.x, a4.y, a4.z, a4.w};
                    const float br[4] = {b4.x, b4.y, b4.z, b4.w};
#pragma unroll
                    for (int i = 0; i < 4; ++i)
#pragma unroll
                        for (int j = 0; j < 4; ++j)
                            acc[i][j] = fmaf(ar[i], br[j], acc[i][j]);
                }
                __syncthreads();
            }

            // regroup gates through shared memory
#pragma unroll
            for (int i = 0; i < 4; ++i)
#pragma unroll
                for (int j = 0; j < 4; ++j)
                    Zs[ty * 4 + i][tx * 4 + j] = acc[i][j];
            __syncthreads();

            const bool keep = (t < elen);
#pragma unroll
            for (int e = 0; e < 4; ++e) {
                const int jj = ejj0 + e;
                const int j  = j0 + jj;
                const float zi = Zs[em][jj]      + bl[j];
                const float zf = Zs[em][16 + jj] + bl[Hh + j];
                const float zg = Zs[em][32 + jj] + bl[2 * Hh + j];
                const float zo = Zs[em][48 + jj] + bl[3 * Hh + j];

                const float ig = sigf(zi);
                const float fg = sigf(zf);
                const float gg = tanhf(zg);
                const float og = sigf(zo);

                const float cold = g_c[layer][ebrow][j];
                const float nc = fg * cold + ig * gg;
                const float nh = og * tanhf(nc);

                g_c[layer][ebrow][j] = keep ? nc : cold;
                const float hold = hin[ebrow * Hh + j];
                hout[ebrow * Hh + j] = keep ? nh : hold;

                if (layer == 0) {
                    g_hbuf[s & 1][ebrow][j] = nh;                 // unmasked nh feeds layer 1
                } else {
                    out[((size_t)ebrow * Tt + t) * Hh + j] = nh;  // top-layer output
                }
            }
            __syncthreads();   // protect Zs before next iteration reuses it
        }
        grid_barrier(base + bar++);
    }
}

extern "C" void kernel_launch(void* const* d_in, const int* in_sizes, int n_in,
                              void* d_out, int out_size) {
    const float* x       = (const float*)d_in[0];
    const float* h_masks = (const float*)d_in[1];
    const float* Wi      = (const float*)d_in[2];
    const float* Wh      = (const float*)d_in[3];
    const float* bias    = (const float*)d_in[4];
    const float* c0      = (const float*)d_in[5];
    const float* h0      = (const float*)d_in[6];
    const int*   lengths = (const int*)d_in[7];
    float* out = (float*)d_out;

    (void)in_sizes; (void)n_in; (void)out_size;

    dim3 grid(Hh / NH, Bb / BM, Ll);  // (32, 2, 2) = 128 blocks, one wave
    lstm_persistent<<<grid, 256>>>(x, h_masks, Wi, Wh, bias, c0, h0, lengths, out);
}